// round 1
// baseline (speedup 1.0000x reference)
#include <cuda_runtime.h>

#define BB 16
#define TT 64
#define F0D 8
#define NN 100
#define NEXD 15
#define LD 16            // NEX+1
#define F1C 32
#define F2C 64
#define BT (BB*TT)       // 1024
#define MTOT (BT*NN)     // 102400
#define PLANE (BT*F0D*NN) // 819200

// Scratch (static __device__ — no allocation at runtime)
__device__ float Zbuf[16 * PLANE];          // [k][bt][f][n]   52.4 MB
__device__ float Q1buf[F1C * 6 * MTOT];     // [c*6+i][g]      78.6 MB
__device__ float Q2buf[F2C * 2 * MTOT];     // [d*2+i][g]      52.4 MB

// ---------------------------------------------------------------------------
// k=0 plane: Zbuf[0] = x
// ---------------------------------------------------------------------------
__global__ void copy_x_kernel(const float* __restrict__ x) {
    int i = blockIdx.x * blockDim.x + threadIdx.x;   // PLANE/4 threads
    float4* dst = reinterpret_cast<float4*>(Zbuf);
    const float4* src = reinterpret_cast<const float4*>(x);
    if (i < PLANE / 4) dst[i] = src[i];
}

// ---------------------------------------------------------------------------
// One diffusion step: Z[k][b,t] = Z[k-1][b,t-1] @ S[b,t]   (zero at t==0)
// CTA = one (b,t). 128 threads; threads 0..99 each own output column m.
// ---------------------------------------------------------------------------
__global__ void diff_step_kernel(const float* __restrict__ S, int k) {
    int bt = blockIdx.x;          // 0..1023
    int t = bt & (TT - 1);
    float* out = Zbuf + (size_t)k * PLANE + (size_t)bt * (F0D * NN);
    int tid = threadIdx.x;

    if (t == 0) {
        for (int i = tid; i < F0D * NN; i += blockDim.x) out[i] = 0.f;
        return;
    }

    __shared__ __align__(16) float ins[F0D * NN];
    const float* in = Zbuf + (size_t)(k - 1) * PLANE + (size_t)(bt - 1) * (F0D * NN);
    for (int i = tid; i < F0D * NN; i += 128) ins[i] = in[i];
    __syncthreads();

    if (tid < NN) {
        const float* Srow = S + (size_t)bt * (NN * NN) + tid;  // S[bt][n][m], m = tid
        float acc[F0D];
#pragma unroll
        for (int f = 0; f < F0D; f++) acc[f] = 0.f;

#pragma unroll 5
        for (int n4 = 0; n4 < NN; n4 += 4) {
            float s0 = Srow[(n4 + 0) * NN];
            float s1 = Srow[(n4 + 1) * NN];
            float s2 = Srow[(n4 + 2) * NN];
            float s3 = Srow[(n4 + 3) * NN];
#pragma unroll
            for (int f = 0; f < F0D; f++) {
                float4 v = *reinterpret_cast<const float4*>(&ins[f * NN + n4]);
                acc[f] = fmaf(v.x, s0, acc[f]);
                acc[f] = fmaf(v.y, s1, acc[f]);
                acc[f] = fmaf(v.z, s2, acc[f]);
                acc[f] = fmaf(v.w, s3, acc[f]);
            }
        }
#pragma unroll
        for (int f = 0; f < F0D; f++) out[f * NN + tid] = acc[f];
    }
}

// ---------------------------------------------------------------------------
// conv1 (K=4) + relu + maxpool2 : z[8][16] -> Q1[32][6]   (thread = node g)
// ---------------------------------------------------------------------------
__global__ void __launch_bounds__(256) conv1_kernel(const float* __restrict__ w1,
                                                    const float* __restrict__ b1) {
    __shared__ __align__(16) float w1s[F1C * F0D * 4];
    __shared__ float b1s[F1C];
    int tid = threadIdx.x;
    for (int i = tid; i < F1C * F0D * 4; i += 256) w1s[i] = w1[i];
    if (tid < F1C) b1s[tid] = b1[tid];
    __syncthreads();

    int g = blockIdx.x * 256 + tid;          // 0..102399
    int bt = g / NN, n = g - bt * NN;
    const float* zb = Zbuf + (size_t)bt * (F0D * NN) + n;

    float zr[F0D * LD];
#pragma unroll
    for (int k = 0; k < LD; k++)
#pragma unroll
        for (int f = 0; f < F0D; f++)
            zr[f * LD + k] = zb[(size_t)k * PLANE + f * NN];

#pragma unroll
    for (int i = 0; i < 6; i++) {
        for (int c = 0; c < F1C; c++) {      // rolled: small code, SMEM-indexed weights
            float a0 = b1s[c], a1 = a0;
            const float4* wc = reinterpret_cast<const float4*>(&w1s[c * 32]);
#pragma unroll
            for (int f = 0; f < F0D; f++) {
                float4 w = wc[f];
                a0 = fmaf(zr[f * LD + 2 * i + 0], w.x, a0);
                a1 = fmaf(zr[f * LD + 2 * i + 1], w.x, a1);
                a0 = fmaf(zr[f * LD + 2 * i + 1], w.y, a0);
                a1 = fmaf(zr[f * LD + 2 * i + 2], w.y, a1);
                a0 = fmaf(zr[f * LD + 2 * i + 2], w.z, a0);
                a1 = fmaf(zr[f * LD + 2 * i + 3], w.z, a1);
                a0 = fmaf(zr[f * LD + 2 * i + 3], w.w, a0);
                a1 = fmaf(zr[f * LD + 2 * i + 4], w.w, a1);
            }
            Q1buf[(c * 6 + i) * MTOT + g] = fmaxf(fmaxf(a0, a1), 0.f);
        }
    }
}

// ---------------------------------------------------------------------------
// conv2 (K=3) + relu + maxpool2 : Q1[32][6] -> Q2[64][2]  (thread = node g)
// ---------------------------------------------------------------------------
__global__ void __launch_bounds__(256) conv2_kernel(const float* __restrict__ w2,
                                                    const float* __restrict__ b2) {
    __shared__ __align__(16) float w2s[F2C * F1C * 3];
    __shared__ float b2s[F2C];
    int tid = threadIdx.x;
    for (int i = tid; i < F2C * F1C * 3; i += 256) w2s[i] = w2[i];
    if (tid < F2C) b2s[tid] = b2[tid];
    __syncthreads();

    int g = blockIdx.x * 256 + tid;

#pragma unroll
    for (int i = 0; i < 2; i++) {            // pooled output position
        float qw[F1C * 4];                   // Q1 columns 2i..2i+3, all 32 channels
#pragma unroll
        for (int c = 0; c < F1C; c++)
#pragma unroll
            for (int col = 0; col < 4; col++)
                qw[c * 4 + col] = Q1buf[(c * 6 + 2 * i + col) * MTOT + g];

        for (int d = 0; d < F2C; d++) {      // rolled channel loop
            float a0 = b2s[d], a1 = a0;
            const float4* wd = reinterpret_cast<const float4*>(&w2s[d * 96]);
#pragma unroll
            for (int cc = 0; cc < 24; cc++) {
                float4 w = wd[cc];
                int l = cc * 4;
                { int c = (l + 0) / 3, j = (l + 0) % 3;
                  a0 = fmaf(qw[c * 4 + j], w.x, a0); a1 = fmaf(qw[c * 4 + j + 1], w.x, a1); }
                { int c = (l + 1) / 3, j = (l + 1) % 3;
                  a0 = fmaf(qw[c * 4 + j], w.y, a0); a1 = fmaf(qw[c * 4 + j + 1], w.y, a1); }
                { int c = (l + 2) / 3, j = (l + 2) % 3;
                  a0 = fmaf(qw[c * 4 + j], w.z, a0); a1 = fmaf(qw[c * 4 + j + 1], w.z, a1); }
                { int c = (l + 3) / 3, j = (l + 3) % 3;
                  a0 = fmaf(qw[c * 4 + j], w.w, a0); a1 = fmaf(qw[c * 4 + j + 1], w.w, a1); }
            }
            Q2buf[(d * 2 + i) * MTOT + g] = fmaxf(fmaxf(a0, a1), 0.f);
        }
    }
}

// ---------------------------------------------------------------------------
// fc1 + relu + fc2 : Q2[128] -> out[5]   (thread = node g)
// out layout: [b][t][o][n]
// ---------------------------------------------------------------------------
__global__ void __launch_bounds__(256) fc_kernel(const float* __restrict__ fc1w,
                                                 const float* __restrict__ fc1b,
                                                 const float* __restrict__ fc2w,
                                                 const float* __restrict__ fc2b,
                                                 float* __restrict__ out) {
    __shared__ __align__(16) float w1s[64 * 128];
    __shared__ float b1s[64];
    __shared__ float w2s[5 * 64];
    __shared__ float b2s[5];
    int tid = threadIdx.x;
    for (int i = tid; i < 64 * 128; i += 256) w1s[i] = fc1w[i];
    if (tid < 64) b1s[tid] = fc1b[tid];
    for (int i = tid; i < 5 * 64; i += 256) w2s[i] = fc2w[i];
    if (tid < 5) b2s[tid] = fc2b[tid];
    __syncthreads();

    int g = blockIdx.x * 256 + tid;

    float q[128];
#pragma unroll
    for (int r = 0; r < 128; r++) q[r] = Q2buf[r * MTOT + g];

    float o[5];
#pragma unroll
    for (int oo = 0; oo < 5; oo++) o[oo] = b2s[oo];

    for (int u = 0; u < 64; u++) {           // rolled hidden-unit loop
        const float4* wu = reinterpret_cast<const float4*>(&w1s[u * 128]);
        float h0 = b1s[u], h1 = 0.f, h2 = 0.f, h3 = 0.f;  // 4 chains for ILP
#pragma unroll
        for (int r4 = 0; r4 < 32; r4 += 4) {
            float4 wa = wu[r4 + 0];
            h0 = fmaf(q[(r4 + 0) * 4 + 0], wa.x, h0);
            h1 = fmaf(q[(r4 + 0) * 4 + 1], wa.y, h1);
            h2 = fmaf(q[(r4 + 0) * 4 + 2], wa.z, h2);
            h3 = fmaf(q[(r4 + 0) * 4 + 3], wa.w, h3);
            float4 wb = wu[r4 + 1];
            h0 = fmaf(q[(r4 + 1) * 4 + 0], wb.x, h0);
            h1 = fmaf(q[(r4 + 1) * 4 + 1], wb.y, h1);
            h2 = fmaf(q[(r4 + 1) * 4 + 2], wb.z, h2);
            h3 = fmaf(q[(r4 + 1) * 4 + 3], wb.w, h3);
            float4 wc = wu[r4 + 2];
            h0 = fmaf(q[(r4 + 2) * 4 + 0], wc.x, h0);
            h1 = fmaf(q[(r4 + 2) * 4 + 1], wc.y, h1);
            h2 = fmaf(q[(r4 + 2) * 4 + 2], wc.z, h2);
            h3 = fmaf(q[(r4 + 2) * 4 + 3], wc.w, h3);
            float4 wd = wu[r4 + 3];
            h0 = fmaf(q[(r4 + 3) * 4 + 0], wd.x, h0);
            h1 = fmaf(q[(r4 + 3) * 4 + 1], wd.y, h1);
            h2 = fmaf(q[(r4 + 3) * 4 + 2], wd.z, h2);
            h3 = fmaf(q[(r4 + 3) * 4 + 3], wd.w, h3);
        }
        float h = fmaxf((h0 + h1) + (h2 + h3), 0.f);
#pragma unroll
        for (int oo = 0; oo < 5; oo++) o[oo] = fmaf(h, w2s[oo * 64 + u], o[oo]);
    }

    int bt = g / NN, n = g - bt * NN;
#pragma unroll
    for (int oo = 0; oo < 5; oo++)
        out[(size_t)(bt * 5 + oo) * NN + n] = o[oo];
}

// ---------------------------------------------------------------------------
// Launch: copy x -> Z[0]; 15 diffusion steps; conv1; conv2; fc.
// All on the default stream (graph-capturable, no allocs, no syncs).
// ---------------------------------------------------------------------------
extern "C" void kernel_launch(void* const* d_in, const int* in_sizes, int n_in,
                              void* d_out, int out_size) {
    const float* x      = (const float*)d_in[0];
    const float* S      = (const float*)d_in[1];
    const float* conv1w = (const float*)d_in[2];
    const float* conv1b = (const float*)d_in[3];
    const float* conv2w = (const float*)d_in[4];
    const float* conv2b = (const float*)d_in[5];
    const float* fc1w   = (const float*)d_in[6];
    const float* fc1b   = (const float*)d_in[7];
    const float* fc2w   = (const float*)d_in[8];
    const float* fc2b   = (const float*)d_in[9];
    float* out = (float*)d_out;

    copy_x_kernel<<<(PLANE / 4 + 255) / 256, 256>>>(x);

    for (int k = 1; k <= NEXD; k++)
        diff_step_kernel<<<BT, 128>>>(S, k);

    conv1_kernel<<<MTOT / 256, 256>>>(conv1w, conv1b);
    conv2_kernel<<<MTOT / 256, 256>>>(conv2w, conv2b);
    fc_kernel<<<MTOT / 256, 256>>>(fc1w, fc1b, fc2w, fc2b, out);
}

// round 7
// speedup vs baseline: 1.6280x; 1.6280x over previous
#include <cuda_runtime.h>
#include <cstdint>

#define BB 16
#define TT 64
#define F0D 8
#define NN 100
#define NEXD 15
#define LD 16            // NEX+1
#define F1C 32
#define F2C 64
#define BT (BB*TT)       // 1024
#define MTOT (BT*NN)     // 102400
#define PLANE (BT*F0D*NN) // 819200

// Scratch (static __device__ — no allocation at runtime)
__device__ float Zbuf[16 * PLANE];          // [k][bt][f][n]  (plane 0 unused; k=0 comes from x)
__device__ float Q1buf[F1C * 6 * MTOT];     // [c*6+i][g]
__device__ float Q2buf[F2C * 2 * MTOT];     // [d*2+i][g]

// ---------------------------------------------------------------------------
// Fused diffusion along diagonal chains.
// Chain (b,s): z_0 = x[b,s]; for k=1..K:  z_k = z_{k-1} @ S[b, s+k],
// written to Zbuf[k] at t = s+k.  (z_k[t] = x[t-k] @ S[t-k+1] ... @ S[t])
// CTA = one chain. 160 threads: warps 0-3 compute (lanes 0..99 = column m),
// warp 4 = cp.async loader double-buffering the 40KB S matrix.
// z ping-pongs in SMEM; S prefetched one step ahead.
// ---------------------------------------------------------------------------
__global__ void __launch_bounds__(160) diff_chain_kernel(const float* __restrict__ x,
                                                         const float* __restrict__ S) {
    extern __shared__ float dsm[];
    float* Sb0 = dsm;                 // S buffers: 2 x 10000 floats
    float* Sb1 = dsm + 10000;
    float* zb0 = dsm + 20000;         // z buffers: 2 x 8*104 floats (rows padded to 104)
    float* zb1 = dsm + 20000 + 832;

    int blk = blockIdx.x;
    int b = blk >> 6, s = blk & 63;
    int K = (NEXD < (63 - s)) ? NEXD : (63 - s);
    if (K <= 0) return;               // s = 63: no work (all threads exit together)
    int tid = threadIdx.x;

    const float* Sg = S + (size_t)(b * TT + s) * (NN * NN);   // S[b][s+k] = Sg + k*10000

    if (tid >= 128) {
        // loader prologue: S_1 -> Sb1
        int lane = tid - 128;
        const float4* src = reinterpret_cast<const float4*>(Sg + NN * NN);
        unsigned dst = (unsigned)__cvta_generic_to_shared(Sb1);
        for (int i = lane; i < 2500; i += 32)
            asm volatile("cp.async.cg.shared.global [%0], [%1], 16;"
                         :: "r"(dst + i * 16), "l"(src + i));
        asm volatile("cp.async.commit_group;");
    } else {
        // load z_0 = x[b][s] into zb0 (row-padded layout [f][104])
        const float* xr = x + (size_t)(b * TT + s) * (F0D * NN);
        for (int i = tid; i < F0D * NN; i += 128) {
            int f = i / NN, n = i - f * NN;
            zb0[f * 104 + n] = xr[i];
        }
    }

    float* zp = zb0;
    float* zc = zb1;
    for (int k = 1; k <= K; k++) {
        __syncthreads();              // (A) compute k-1 done -> S buffer being refilled is free
        if (tid >= 128) {
            if (k < K) {
                int lane = tid - 128;
                const float4* src = reinterpret_cast<const float4*>(Sg + (size_t)(k + 1) * (NN * NN));
                unsigned dst = (unsigned)__cvta_generic_to_shared(((k + 1) & 1) ? Sb1 : Sb0);
                for (int i = lane; i < 2500; i += 32)
                    asm volatile("cp.async.cg.shared.global [%0], [%1], 16;"
                                 :: "r"(dst + i * 16), "l"(src + i));
                asm volatile("cp.async.commit_group;");
                asm volatile("cp.async.wait_group 1;");   // S_k complete, S_{k+1} in flight
            } else {
                asm volatile("cp.async.wait_group 0;");   // S_K complete
            }
        }
        __syncthreads();              // (B) S_k visible to compute warps
        if (tid < NN) {
            const float* Ss = (k & 1) ? Sb1 : Sb0;
            float acc[F0D];
#pragma unroll
            for (int f = 0; f < F0D; f++) acc[f] = 0.f;
#pragma unroll 5
            for (int n4 = 0; n4 < NN; n4 += 4) {
                float s0 = Ss[(n4 + 0) * NN + tid];
                float s1 = Ss[(n4 + 1) * NN + tid];
                float s2 = Ss[(n4 + 2) * NN + tid];
                float s3 = Ss[(n4 + 3) * NN + tid];
#pragma unroll
                for (int f = 0; f < F0D; f++) {
                    float4 v = *reinterpret_cast<const float4*>(&zp[f * 104 + n4]);
                    acc[f] = fmaf(v.x, s0, acc[f]);
                    acc[f] = fmaf(v.y, s1, acc[f]);
                    acc[f] = fmaf(v.z, s2, acc[f]);
                    acc[f] = fmaf(v.w, s3, acc[f]);
                }
            }
            float* outp = Zbuf + (size_t)k * PLANE + (size_t)(b * TT + s + k) * (F0D * NN);
#pragma unroll
            for (int f = 0; f < F0D; f++) {
                zc[f * 104 + tid] = acc[f];
                outp[f * NN + tid] = acc[f];
            }
        }
        float* tmp = zp; zp = zc; zc = tmp;
    }
}

// ---------------------------------------------------------------------------
// conv1 (K=4) + relu + maxpool2 : z[8][16] -> Q1[32][6]   (thread = node g)
// k=0 plane read straight from x (same [bt][f][n] layout); planes with k > t
// are implicit zeros (never written by diff_chain).
// ---------------------------------------------------------------------------
__global__ void __launch_bounds__(256) conv1_kernel(const float* __restrict__ x,
                                                    const float* __restrict__ w1,
                                                    const float* __restrict__ b1) {
    __shared__ __align__(16) float w1s[F1C * F0D * 4];
    __shared__ float b1s[F1C];
    int tid = threadIdx.x;
    for (int i = tid; i < F1C * F0D * 4; i += 256) w1s[i] = w1[i];
    if (tid < F1C) b1s[tid] = b1[tid];
    __syncthreads();

    int g = blockIdx.x * 256 + tid;
    int bt = g / NN, n = g - bt * NN;
    int t = bt & (TT - 1);
    const float* zb = Zbuf + (size_t)bt * (F0D * NN) + n;
    const float* xb = x + (size_t)bt * (F0D * NN) + n;

    float zr[F0D * LD];
#pragma unroll
    for (int f = 0; f < F0D; f++)
        zr[f * LD + 0] = xb[f * NN];
#pragma unroll
    for (int k = 1; k < LD; k++) {
        bool valid = (k <= t);
#pragma unroll
        for (int f = 0; f < F0D; f++)
            zr[f * LD + k] = valid ? zb[(size_t)k * PLANE + f * NN] : 0.f;
    }

#pragma unroll
    for (int i = 0; i < 6; i++) {
        for (int c = 0; c < F1C; c++) {
            float a0 = b1s[c], a1 = a0;
            const float4* wc = reinterpret_cast<const float4*>(&w1s[c * 32]);
#pragma unroll
            for (int f = 0; f < F0D; f++) {
                float4 w = wc[f];
                a0 = fmaf(zr[f * LD + 2 * i + 0], w.x, a0);
                a1 = fmaf(zr[f * LD + 2 * i + 1], w.x, a1);
                a0 = fmaf(zr[f * LD + 2 * i + 1], w.y, a0);
                a1 = fmaf(zr[f * LD + 2 * i + 2], w.y, a1);
                a0 = fmaf(zr[f * LD + 2 * i + 2], w.z, a0);
                a1 = fmaf(zr[f * LD + 2 * i + 3], w.z, a1);
                a0 = fmaf(zr[f * LD + 2 * i + 3], w.w, a0);
                a1 = fmaf(zr[f * LD + 2 * i + 4], w.w, a1);
            }
            Q1buf[(c * 6 + i) * MTOT + g] = fmaxf(fmaxf(a0, a1), 0.f);
        }
    }
}

// ---------------------------------------------------------------------------
// conv2 (K=3) + relu + maxpool2 : Q1[32][6] -> Q2[64][2]  (thread = node g)
// ---------------------------------------------------------------------------
__global__ void __launch_bounds__(256) conv2_kernel(const float* __restrict__ w2,
                                                    const float* __restrict__ b2) {
    __shared__ __align__(16) float w2s[F2C * F1C * 3];
    __shared__ float b2s[F2C];
    int tid = threadIdx.x;
    for (int i = tid; i < F2C * F1C * 3; i += 256) w2s[i] = w2[i];
    if (tid < F2C) b2s[tid] = b2[tid];
    __syncthreads();

    int g = blockIdx.x * 256 + tid;

#pragma unroll
    for (int i = 0; i < 2; i++) {
        float qw[F1C * 4];
#pragma unroll
        for (int c = 0; c < F1C; c++)
#pragma unroll
            for (int col = 0; col < 4; col++)
                qw[c * 4 + col] = Q1buf[(c * 6 + 2 * i + col) * MTOT + g];

        for (int d = 0; d < F2C; d++) {
            float a0 = b2s[d], a1 = a0;
            const float4* wd = reinterpret_cast<const float4*>(&w2s[d * 96]);
#pragma unroll
            for (int cc = 0; cc < 24; cc++) {
                float4 w = wd[cc];
                int l = cc * 4;
                { int c = (l + 0) / 3, j = (l + 0) % 3;
                  a0 = fmaf(qw[c * 4 + j], w.x, a0); a1 = fmaf(qw[c * 4 + j + 1], w.x, a1); }
                { int c = (l + 1) / 3, j = (l + 1) % 3;
                  a0 = fmaf(qw[c * 4 + j], w.y, a0); a1 = fmaf(qw[c * 4 + j + 1], w.y, a1); }
                { int c = (l + 2) / 3, j = (l + 2) % 3;
                  a0 = fmaf(qw[c * 4 + j], w.z, a0); a1 = fmaf(qw[c * 4 + j + 1], w.z, a1); }
                { int c = (l + 3) / 3, j = (l + 3) % 3;
                  a0 = fmaf(qw[c * 4 + j], w.w, a0); a1 = fmaf(qw[c * 4 + j + 1], w.w, a1); }
            }
            Q2buf[(d * 2 + i) * MTOT + g] = fmaxf(fmaxf(a0, a1), 0.f);
        }
    }
}

// ---------------------------------------------------------------------------
// fc1 + relu + fc2 : Q2[128] -> out[5]   (thread = node g), out [b][t][o][n]
// ---------------------------------------------------------------------------
__global__ void __launch_bounds__(256) fc_kernel(const float* __restrict__ fc1w,
                                                 const float* __restrict__ fc1b,
                                                 const float* __restrict__ fc2w,
                                                 const float* __restrict__ fc2b,
                                                 float* __restrict__ out) {
    __shared__ __align__(16) float w1s[64 * 128];
    __shared__ float b1s[64];
    __shared__ float w2s[5 * 64];
    __shared__ float b2s[5];
    int tid = threadIdx.x;
    for (int i = tid; i < 64 * 128; i += 256) w1s[i] = fc1w[i];
    if (tid < 64) b1s[tid] = fc1b[tid];
    for (int i = tid; i < 5 * 64; i += 256) w2s[i] = fc2w[i];
    if (tid < 5) b2s[tid] = fc2b[tid];
    __syncthreads();

    int g = blockIdx.x * 256 + tid;

    float q[128];
#pragma unroll
    for (int r = 0; r < 128; r++) q[r] = Q2buf[r * MTOT + g];

    float o[5];
#pragma unroll
    for (int oo = 0; oo < 5; oo++) o[oo] = b2s[oo];

    for (int u = 0; u < 64; u++) {
        const float4* wu = reinterpret_cast<const float4*>(&w1s[u * 128]);
        float h0 = b1s[u], h1 = 0.f, h2 = 0.f, h3 = 0.f;
#pragma unroll
        for (int r4 = 0; r4 < 32; r4 += 4) {
            float4 wa = wu[r4 + 0];
            h0 = fmaf(q[(r4 + 0) * 4 + 0], wa.x, h0);
            h1 = fmaf(q[(r4 + 0) * 4 + 1], wa.y, h1);
            h2 = fmaf(q[(r4 + 0) * 4 + 2], wa.z, h2);
            h3 = fmaf(q[(r4 + 0) * 4 + 3], wa.w, h3);
            float4 wb = wu[r4 + 1];
            h0 = fmaf(q[(r4 + 1) * 4 + 0], wb.x, h0);
            h1 = fmaf(q[(r4 + 1) * 4 + 1], wb.y, h1);
            h2 = fmaf(q[(r4 + 1) * 4 + 2], wb.z, h2);
            h3 = fmaf(q[(r4 + 1) * 4 + 3], wb.w, h3);
            float4 wc = wu[r4 + 2];
            h0 = fmaf(q[(r4 + 2) * 4 + 0], wc.x, h0);
            h1 = fmaf(q[(r4 + 2) * 4 + 1], wc.y, h1);
            h2 = fmaf(q[(r4 + 2) * 4 + 2], wc.z, h2);
            h3 = fmaf(q[(r4 + 2) * 4 + 3], wc.w, h3);
            float4 wd = wu[r4 + 3];
            h0 = fmaf(q[(r4 + 3) * 4 + 0], wd.x, h0);
            h1 = fmaf(q[(r4 + 3) * 4 + 1], wd.y, h1);
            h2 = fmaf(q[(r4 + 3) * 4 + 2], wd.z, h2);
            h3 = fmaf(q[(r4 + 3) * 4 + 3], wd.w, h3);
        }
        float h = fmaxf((h0 + h1) + (h2 + h3), 0.f);
#pragma unroll
        for (int oo = 0; oo < 5; oo++) o[oo] = fmaf(h, w2s[oo * 64 + u], o[oo]);
    }

    int bt = g / NN, n = g - bt * NN;
#pragma unroll
    for (int oo = 0; oo < 5; oo++)
        out[(size_t)(bt * 5 + oo) * NN + n] = o[oo];
}

// ---------------------------------------------------------------------------
// Launch: fused diffusion (1 launch); conv1 (reads x for k=0); conv2; fc.
// ---------------------------------------------------------------------------
extern "C" void kernel_launch(void* const* d_in, const int* in_sizes, int n_in,
                              void* d_out, int out_size) {
    const float* x      = (const float*)d_in[0];
    const float* S      = (const float*)d_in[1];
    const float* conv1w = (const float*)d_in[2];
    const float* conv1b = (const float*)d_in[3];
    const float* conv2w = (const float*)d_in[4];
    const float* conv2b = (const float*)d_in[5];
    const float* fc1w   = (const float*)d_in[6];
    const float* fc1b   = (const float*)d_in[7];
    const float* fc2w   = (const float*)d_in[8];
    const float* fc2b   = (const float*)d_in[9];
    float* out = (float*)d_out;

    const int dsm_bytes = (2 * NN * NN + 2 * F0D * 104) * (int)sizeof(float);  // 86656
    cudaFuncSetAttribute(diff_chain_kernel,
                         cudaFuncAttributeMaxDynamicSharedMemorySize, dsm_bytes);

    diff_chain_kernel<<<BT, 160, dsm_bytes>>>(x, S);
    conv1_kernel<<<MTOT / 256, 256>>>(x, conv1w, conv1b);
    conv2_kernel<<<MTOT / 256, 256>>>(conv2w, conv2b);
    fc_kernel<<<MTOT / 256, 256>>>(fc1w, fc1b, fc2w, fc2b, out);
}